// round 1
// baseline (speedup 1.0000x reference)
#include <cuda_runtime.h>
#include <math.h>

#define BATCH 2048
#define XF    1024
#define G     16
#define ROWSPLIT 32
#define ROWS_PER (BATCH / ROWSPLIT)   // 64

// Scratch (allocation-free: __device__ globals)
__device__ float g_part0[ROWSPLIT * XF];
__device__ float g_part1[ROWSPLIT * XF];
__device__ float g_part2[ROWSPLIT * XF];
__device__ float g_mean[XF];
__device__ float g_a[XF];
__device__ float g_b[XF];

// Pass 1a: per-column partial sums of xf (deterministic tree, no atomics).
// grid = (4, 32), block = 256. Thread t of block-x b owns column b*256+t.
__global__ void k_sum_partial(const float* __restrict__ xf) {
    int col = blockIdx.x * 256 + threadIdx.x;
    int rs  = blockIdx.y;
    const float* p = xf + (size_t)rs * ROWS_PER * XF + col;
    float s = 0.f;
#pragma unroll 8
    for (int r = 0; r < ROWS_PER; r++) s += p[(size_t)r * XF];
    g_part0[rs * XF + col] = s;
}

// Pass 1b: fold 32 partials -> column mean. grid = (4), block = 256.
__global__ void k_sum_reduce() {
    int col = blockIdx.x * 256 + threadIdx.x;
    float s = 0.f;
#pragma unroll
    for (int r = 0; r < ROWSPLIT; r++) s += g_part0[r * XF + col];
    g_mean[col] = s * (1.0f / BATCH);
}

// Pass 2a: partial sum / sumsq of relu(xf - mean) per column.
__global__ void k_stats_partial(const float* __restrict__ xf) {
    int col = blockIdx.x * 256 + threadIdx.x;
    int rs  = blockIdx.y;
    float m = g_mean[col];
    const float* p = xf + (size_t)rs * ROWS_PER * XF + col;
    float s1 = 0.f, s2 = 0.f;
#pragma unroll 8
    for (int r = 0; r < ROWS_PER; r++) {
        float v = p[(size_t)r * XF] - m;
        v = v > 0.f ? v : 0.f;
        s1 += v;
        s2 += v * v;
    }
    g_part1[rs * XF + col] = s1;
    g_part2[rs * XF + col] = s2;
}

// Pass 2b: mu, sd (ddof=1), fold wp into per-column affine a,b.
__global__ void k_stats_reduce(const float* __restrict__ wp) {
    int col = blockIdx.x * 256 + threadIdx.x;
    float s1 = 0.f, s2 = 0.f;
#pragma unroll
    for (int r = 0; r < ROWSPLIT; r++) {
        s1 += g_part1[r * XF + col];
        s2 += g_part2[r * XF + col];
    }
    float mu  = s1 * (1.0f / BATCH);
    float var = (s2 - (float)BATCH * mu * mu) * (1.0f / (BATCH - 1));
    float sd  = sqrtf(var);
    float a   = wp[0] / sd;
    g_a[col] = a;
    g_b[col] = -a * mu;
}

// Pass 3: compute v = a*relu(x-mean)+b once per element, write 16 tiled copies.
// Thread handles 4 columns (float4). grid = BATCH*XF/4/256 = 2048 blocks.
__global__ void k_out(const float* __restrict__ xf, float* __restrict__ out) {
    int idx = blockIdx.x * blockDim.x + threadIdx.x;   // over BATCH * (XF/4)
    int row = idx >> 8;          // XF/4 = 256 float4 per row
    int c4  = idx & 255;
    int col = c4 * 4;

    float4 x = *(const float4*)(xf + (size_t)row * XF + col);
    float4 m = *(const float4*)(g_mean + col);
    float4 a = *(const float4*)(g_a + col);
    float4 b = *(const float4*)(g_b + col);

    float4 v;
    v.x = fmaxf(x.x - m.x, 0.f) * a.x + b.x;
    v.y = fmaxf(x.y - m.y, 0.f) * a.y + b.y;
    v.z = fmaxf(x.z - m.z, 0.f) * a.z + b.z;
    v.w = fmaxf(x.w - m.w, 0.f) * a.w + b.w;

    float* orow = out + (size_t)row * (G * XF) + col;
#pragma unroll
    for (int k = 0; k < G; k++)
        *(float4*)(orow + (size_t)k * XF) = v;
}

extern "C" void kernel_launch(void* const* d_in, const int* in_sizes, int n_in,
                              void* d_out, int out_size) {
    const float* xf = (const float*)d_in[0];
    const float* wp = (const float*)d_in[1];
    float* out = (float*)d_out;

    k_sum_partial<<<dim3(XF / 256, ROWSPLIT), 256>>>(xf);
    k_sum_reduce<<<XF / 256, 256>>>();
    k_stats_partial<<<dim3(XF / 256, ROWSPLIT), 256>>>(xf);
    k_stats_reduce<<<XF / 256, 256>>>(wp);
    k_out<<<(BATCH * XF / 4) / 256, 256>>>(xf, out);
}

// round 2
// speedup vs baseline: 1.2819x; 1.2819x over previous
#include <cuda_runtime.h>
#include <math.h>

#define BATCH 2048
#define XF    1024
#define G     16
#define ROWSPLIT 32
#define ROWS_PER (BATCH / ROWSPLIT)   // 64

// Scratch (allocation-free: __device__ globals)
__device__ float g_part0[ROWSPLIT * XF];   // partial sums of xf
__device__ float g_part1[ROWSPLIT * XF];   // partial sums of relu(x-mean)
__device__ float g_part2[ROWSPLIT * XF];   // partial sums of squares
__device__ float g_mean[XF];

// K1: per-column partial sums of xf. grid=(4,32), block=256.
__global__ void k_sum_partial(const float* __restrict__ xf) {
    int col = blockIdx.x * 256 + threadIdx.x;
    int rs  = blockIdx.y;
    const float* p = xf + (size_t)rs * ROWS_PER * XF + col;
    float s = 0.f;
#pragma unroll 8
    for (int r = 0; r < ROWS_PER; r++) s += p[(size_t)r * XF];
    g_part0[rs * XF + col] = s;
}

// K2: fold partials -> mean inline (redundant per block, L2-cheap), then
// partial sum/sumsq of relu(x-mean). grid=(4,32), block=256.
__global__ void k_stats(const float* __restrict__ xf) {
    int col = blockIdx.x * 256 + threadIdx.x;
    int rs  = blockIdx.y;

    float s = 0.f;
#pragma unroll
    for (int r = 0; r < ROWSPLIT; r++) s += g_part0[r * XF + col];
    float m = s * (1.0f / BATCH);
    if (rs == 0) g_mean[col] = m;

    const float* p = xf + (size_t)rs * ROWS_PER * XF + col;
    float s1 = 0.f, s2 = 0.f;
#pragma unroll 8
    for (int r = 0; r < ROWS_PER; r++) {
        float v = p[(size_t)r * XF] - m;
        v = v > 0.f ? v : 0.f;
        s1 += v;
        s2 += v * v;
    }
    g_part1[rs * XF + col] = s1;
    g_part2[rs * XF + col] = s2;
}

// K3: per-block prologue reduces stats partials for its 64 columns into
// per-column affine (a,b), then writes the 16-way tiled output.
// grid=(16,16): bx = 64-col tile, by = 128-row tile. block=256.
#define COLS_B 64
#define ROWS_B 128
__global__ void k_out(const float* __restrict__ xf,
                      const float* __restrict__ wp,
                      float* __restrict__ out) {
    __shared__ float s_m[COLS_B], s_a[COLS_B], s_b[COLS_B];
    int tid = threadIdx.x;
    int col0 = blockIdx.x * COLS_B;

    if (tid < COLS_B) {
        int col = col0 + tid;
        float s1 = 0.f, s2 = 0.f;
#pragma unroll
        for (int r = 0; r < ROWSPLIT; r++) {
            s1 += g_part1[r * XF + col];
            s2 += g_part2[r * XF + col];
        }
        float mu  = s1 * (1.0f / BATCH);
        float var = (s2 - (float)BATCH * mu * mu) * (1.0f / (BATCH - 1));
        float a   = wp[0] * rsqrtf(var);
        s_m[tid] = g_mean[col];
        s_a[tid] = a;
        s_b[tid] = -a * mu;
    }
    __syncthreads();

    int cidx = tid & 15;          // which float4 within 64 cols
    int ridx = tid >> 4;          // 0..15
    int col  = col0 + cidx * 4;

    float4 m = *(const float4*)(s_m + cidx * 4);
    float4 a = *(const float4*)(s_a + cidx * 4);
    float4 b = *(const float4*)(s_b + cidx * 4);

#pragma unroll
    for (int j = 0; j < ROWS_B / 16; j++) {     // 8 rows per thread
        int row = blockIdx.y * ROWS_B + ridx + j * 16;
        float4 x = *(const float4*)(xf + (size_t)row * XF + col);
        float4 v;
        v.x = fmaxf(x.x - m.x, 0.f) * a.x + b.x;
        v.y = fmaxf(x.y - m.y, 0.f) * a.y + b.y;
        v.z = fmaxf(x.z - m.z, 0.f) * a.z + b.z;
        v.w = fmaxf(x.w - m.w, 0.f) * a.w + b.w;

        float* orow = out + (size_t)row * (G * XF) + col;
#pragma unroll
        for (int k = 0; k < G; k++)
            __stcs((float4*)(orow + (size_t)k * XF), v);
    }
}

extern "C" void kernel_launch(void* const* d_in, const int* in_sizes, int n_in,
                              void* d_out, int out_size) {
    const float* xf = (const float*)d_in[0];
    const float* wp = (const float*)d_in[1];
    float* out = (float*)d_out;

    k_sum_partial<<<dim3(XF / 256, ROWSPLIT), 256>>>(xf);
    k_stats<<<dim3(XF / 256, ROWSPLIT), 256>>>(xf);
    k_out<<<dim3(XF / COLS_B, BATCH / ROWS_B), 256>>>(xf, wp, out);
}